// round 16
// baseline (speedup 1.0000x reference)
#include <cuda_runtime.h>
#include <cuda_fp16.h>
#include <math.h>
#include <float.h>
#include <stdint.h>

#define B 8
#define SEQ 12
#define NN 1000
#define E 16000
#define HID 128
#define HEADS 8
#define DH 16
#define M_ROWS (B*NN)          /* 8000 */

#define AT_STRIDE 68
#define GEMM_SMEM (HID*HID*4 + HID*AT_STRIDE*4)   /* FFMA gemm */

/* fp16-mma gemm smem (uint32 words), stride 68 words per row */
#define HS 68
#define A_H_OFF 0
#define A_L_OFF (64*HS)
#define B_H_OFF (2*64*HS)
#define HMMA_SMEM ((2*64*HS + 128*HS)*4)   /* 69632 B */

// ---------------- static device scratch ----------------
__device__ float    g_hin[(size_t)SEQ*B*NN*HID];
__device__ float    g_y  [(size_t)M_ROWS*HID];
__device__ __half   g_hp [(size_t)M_ROWS*HID];
__device__ float    g_k1 [(size_t)M_ROWS*HID];
__device__ float    g_k2 [(size_t)M_ROWS*HID];
__device__ float    g_k3 [(size_t)M_ROWS*HID];
__device__ float    g_tmp[(size_t)M_ROWS*HID];
__device__ float    g_el [(size_t)M_ROWS*HEADS];
__device__ float    g_er [(size_t)M_ROWS*HEADS];
__device__ unsigned g_wh [HID*HID/2];   /* W^T fp16 hi: [n][kword] */
__device__ int      g_cnt[NN];
__device__ int      g_cur[NN];
__device__ int      g_off[NN+1];
__device__ int      g_eidx[E];
__device__ int      g_srcs[E];

// ---------------- helpers ----------------
__device__ __forceinline__ unsigned packh2(float a, float b){
    __half2 t = __floats2half2_rn(a, b);
    unsigned u; memcpy(&u, &t, 4); return u;
}
__device__ __forceinline__ float h_res(float x){
    return x - __half2float(__float2half_rn(x));
}
#define HMMA16(c, a0,a1,a2,a3, b0,b1) \
    asm volatile("mma.sync.aligned.m16n8k16.row.col.f32.f16.f16.f32 " \
        "{%0,%1,%2,%3}, {%4,%5,%6,%7}, {%8,%9}, {%0,%1,%2,%3};" \
        : "+f"((c)[0]), "+f"((c)[1]), "+f"((c)[2]), "+f"((c)[3]) \
        : "r"(a0), "r"(a1), "r"(a2), "r"(a3), "r"(b0), "r"(b1))

// ---------------- fused init: inproj + y=h[:,0] + CSR zero ----------------
__global__ void k_init(const float* __restrict__ inp, const float* __restrict__ w_in,
                       const float* __restrict__ b_in, float* __restrict__ hin,
                       float* __restrict__ y, int* cnt, int* cur){
    int row = blockIdx.x;
    int t = threadIdx.x;
    if (blockIdx.x < 8){
        int q = blockIdx.x*128 + t;
        if (q < NN){ cnt[q] = 0; cur[q] = 0; }
    }
    int b = row / (SEQ*NN);
    int s = (row / NN) % SEQ;
    int n = row % NN;
    float x0 = inp[(size_t)row*2 + 0];
    float x1 = inp[(size_t)row*2 + 1];
    float v = fmaf(x0, w_in[t], fmaf(x1, w_in[HID+t], b_in[t]));
    hin[(((size_t)s*B + b)*NN + n)*HID + t] = v;
    if (s == 0) y[((size_t)b*NN + n)*HID + t] = v;
}

// ---------------- W^T fp16 split: g_wh[n*64 + kword] ----------------
__global__ void k_wsplit(const float* __restrict__ w, unsigned* wh){
    int i = blockIdx.x*256 + threadIdx.x;
    if (i >= HID*HID/2) return;
    int n = i >> 6, kw = i & 63;
    int k0 = kw*2;
    wh[i] = packh2(w[(size_t)k0*HID + n], w[(size_t)(k0+1)*HID + n]);
}

// ---------------- CSR construction (deterministic) ----------------
__global__ void k_csr_count(const int* __restrict__ dst, int* cnt){
    int e = blockIdx.x*blockDim.x + threadIdx.x;
    if (e < E) atomicAdd(&cnt[dst[e]], 1);
}
__global__ void k_csr_scan(const int* __restrict__ cnt, int* off){
    __shared__ int s[1024];
    int t = threadIdx.x;
    s[t] = (t < NN) ? cnt[t] : 0;
    __syncthreads();
    #pragma unroll
    for (int o = 1; o < 1024; o <<= 1){
        int v = (t >= o) ? s[t-o] : 0;
        __syncthreads();
        s[t] += v;
        __syncthreads();
    }
    if (t == 0) off[0] = 0;
    if (t < NN) off[t+1] = s[t];
}
__global__ void k_csr_fill(const int* __restrict__ dst, const int* __restrict__ off,
                           int* cur, int* eidx){
    int e = blockIdx.x*blockDim.x + threadIdx.x;
    if (e < E){
        int d = dst[e];
        int p = atomicAdd(&cur[d], 1);
        eidx[off[d] + p] = e;
    }
}
__global__ void k_csr_sort(const int* __restrict__ off, int* eidx){
    if (threadIdx.x != 0) return;
    int n = blockIdx.x;
    int a = off[n], b = off[n+1];
    for (int i = a+1; i < b; i++){
        int v = eidx[i]; int j = i-1;
        while (j >= a && eidx[j] > v){ eidx[j+1] = eidx[j]; j--; }
        eidx[j+1] = v;
    }
}
__global__ void k_csr_gather(const int* __restrict__ eidx, const int* __restrict__ src,
                             int* __restrict__ srcs){
    int i = blockIdx.x*blockDim.x + threadIdx.x;
    if (i < E) srcs[i] = src[eidx[i]];
}

// ========== fp16 HMMA GEMM (GAT path): hp(fp16) = (A0 + c1*A1) @ W_gat ==========
__global__ void __launch_bounds__(512) k_gemm_h(
    const float* __restrict__ A0, const float* __restrict__ A1, float c1,
    const unsigned* __restrict__ WH,
    __half* __restrict__ Ch,
    float* __restrict__ el, float* __restrict__ er,
    const float* __restrict__ a_l, const float* __restrict__ a_r)
{
    extern __shared__ unsigned hsm[];
    unsigned* sAh = hsm + A_H_OFF;   // [64][HS]
    unsigned* sAl = hsm + A_L_OFF;
    unsigned* sBh = hsm + B_H_OFF;   // [128][HS]

    int tid  = threadIdx.x;
    int lane = tid & 31, w = tid >> 5;
    int row0 = blockIdx.x * 64;
    int mrow = (w & 3) * 16;
    int ncol = (w >> 2) * 32;
    int g = lane >> 2;        // 0..7
    int t = lane & 3;         // 0..3

    // ---- stage B hi (copy, row-padded) ----
    {
        const uint4* H4 = (const uint4*)WH;
        #pragma unroll
        for (int i = tid; i < 2048; i += 512){
            int n = i >> 4, kw = (i & 15) * 4;
            *reinterpret_cast<uint4*>(&sBh[n*HS + kw]) = H4[i];
        }
    }
    // ---- stage A hi/lo (fused axpy + fp16 split) ----
    {
        const float4* A04 = (const float4*)A0;
        const float4* A14 = (const float4*)A1;
        #pragma unroll
        for (int i = tid; i < 64*32; i += 512){
            int r = i >> 5, c4 = i & 31;
            float4 v = A04[(size_t)(row0+r)*32 + c4];
            if (A1){
                float4 u = A14[(size_t)(row0+r)*32 + c4];
                v.x = fmaf(c1,u.x,v.x); v.y = fmaf(c1,u.y,v.y);
                v.z = fmaf(c1,u.z,v.z); v.w = fmaf(c1,u.w,v.w);
            }
            int kw = c4*2;
            sAh[r*HS + kw]     = packh2(v.x, v.y);
            sAh[r*HS + kw + 1] = packh2(v.z, v.w);
            sAl[r*HS + kw]     = packh2(h_res(v.x), h_res(v.y));
            sAl[r*HS + kw + 1] = packh2(h_res(v.z), h_res(v.w));
        }
    }
    __syncthreads();

    float acc[4][4];
    #pragma unroll
    for (int i=0;i<4;i++)
        #pragma unroll
        for (int j=0;j<4;j++) acc[i][j] = 0.f;

    const unsigned* pAh1 = sAh + (mrow + g)*HS;
    const unsigned* pAh2 = pAh1 + 8*HS;
    const unsigned* pAl1 = sAl + (mrow + g)*HS;
    const unsigned* pAl2 = pAl1 + 8*HS;

    #pragma unroll
    for (int ks = 0; ks < 8; ks++){
        int kw = ks*8 + t;
        unsigned ah0 = pAh1[kw], ah1 = pAh2[kw], ah2 = pAh1[kw+4], ah3 = pAh2[kw+4];
        unsigned al0 = pAl1[kw], al1 = pAl2[kw], al2 = pAl1[kw+4], al3 = pAl2[kw+4];
        #pragma unroll
        for (int nt = 0; nt < 4; nt++){
            int bi = (ncol + nt*8 + g)*HS + kw;
            unsigned bh0 = sBh[bi], bh1 = sBh[bi+4];
            HMMA16(acc[nt], ah0,ah1,ah2,ah3, bh0,bh1);
            HMMA16(acc[nt], al0,al1,al2,al3, bh0,bh1);
        }
    }

    // ---- store hp (fp16) ----
    {
        size_t r1 = row0 + mrow + g;
        #pragma unroll
        for (int nt=0; nt<4; nt++){
            int col = ncol + nt*8 + t*2;
            __half2 p0 = __floats2half2_rn(acc[nt][0], acc[nt][1]);
            __half2 p1 = __floats2half2_rn(acc[nt][2], acc[nt][3]);
            *reinterpret_cast<__half2*>(Ch + r1*HID + col)     = p0;
            *reinterpret_cast<__half2*>(Ch + (r1+8)*HID + col) = p1;
        }
    }
    // ---- el/er epilogue (verified fragment layout) ----
    {
        int h0 = ncol >> 4;
        float pl[2][2] = {{0.f,0.f},{0.f,0.f}};
        float pr[2][2] = {{0.f,0.f},{0.f,0.f}};
        #pragma unroll
        for (int nt=0; nt<4; nt++){
            int hp_ = nt >> 1;
            int d   = (nt & 1)*8 + t*2;
            int h   = h0 + hp_;
            float l0 = a_l[h*DH + d],  l1 = a_l[h*DH + d + 1];
            float r0 = a_r[h*DH + d],  r1 = a_r[h*DH + d + 1];
            pl[hp_][0] += acc[nt][0]*l0 + acc[nt][1]*l1;
            pl[hp_][1] += acc[nt][2]*l0 + acc[nt][3]*l1;
            pr[hp_][0] += acc[nt][0]*r0 + acc[nt][1]*r1;
            pr[hp_][1] += acc[nt][2]*r0 + acc[nt][3]*r1;
        }
        #pragma unroll
        for (int hp_=0; hp_<2; hp_++){
            #pragma unroll
            for (int rh=0; rh<2; rh++){
                pl[hp_][rh] += __shfl_xor_sync(0xffffffffu, pl[hp_][rh], 1);
                pl[hp_][rh] += __shfl_xor_sync(0xffffffffu, pl[hp_][rh], 2);
                pr[hp_][rh] += __shfl_xor_sync(0xffffffffu, pr[hp_][rh], 1);
                pr[hp_][rh] += __shfl_xor_sync(0xffffffffu, pr[hp_][rh], 2);
            }
        }
        if (t == 0){
            int r1 = row0 + mrow + g;
            el[(size_t)r1*HEADS + h0]       = pl[0][0];
            el[(size_t)(r1+8)*HEADS + h0]   = pl[0][1];
            el[(size_t)r1*HEADS + h0+1]     = pl[1][0];
            el[(size_t)(r1+8)*HEADS + h0+1] = pl[1][1];
            er[(size_t)r1*HEADS + h0]       = pr[0][0];
            er[(size_t)(r1+8)*HEADS + h0]   = pr[0][1];
            er[(size_t)r1*HEADS + h0+1]     = pr[1][0];
            er[(size_t)(r1+8)*HEADS + h0+1] = pr[1][1];
        }
    }
}

// ---------------- FFMA GEMM (tanh/LN + head path; proven) ----------------
__global__ void __launch_bounds__(512) k_gemm(
    const float* __restrict__ A0,
    const float* __restrict__ W0,
    const float* __restrict__ A2, const float* __restrict__ W1,
    const float* __restrict__ b0, const float* __restrict__ b1,
    float* __restrict__ C, int act, int doLN)
{
    extern __shared__ float fsm[];
    float* sW  = fsm;
    float* sAT = fsm + HID*HID;

    int row0 = blockIdx.x * 64;
    int tid = threadIdx.x;
    int tx = tid & 31, ty = tid >> 5;
    int col0 = tx * 4;

    float acc[4][4];
    #pragma unroll
    for (int i=0;i<4;i++)
        #pragma unroll
        for (int j=0;j<4;j++) acc[i][j] = 0.f;

    {
        const float4* W4 = (const float4*)W0;
        float4* sW4 = (float4*)sW;
        #pragma unroll
        for (int i = tid; i < HID*32; i += 512) sW4[i] = W4[i];
        const float4* A04 = (const float4*)A0;
        #pragma unroll
        for (int i = tid; i < 64*32; i += 512){
            int r = i >> 5, c4 = i & 31;
            float4 v = A04[(size_t)(row0+r)*32 + c4];
            int k0 = c4*4;
            sAT[(k0+0)*AT_STRIDE + r] = v.x;
            sAT[(k0+1)*AT_STRIDE + r] = v.y;
            sAT[(k0+2)*AT_STRIDE + r] = v.z;
            sAT[(k0+3)*AT_STRIDE + r] = v.w;
        }
    }
    __syncthreads();
    {
        const float4* sW4 = (const float4*)sW;
        float4 w = sW4[tx];
        float4 a = *reinterpret_cast<const float4*>(sAT + ty*4);
        #pragma unroll 4
        for (int k = 0; k < HID; k++){
            int kn = (k+1) & 127;
            float4 wn = sW4[kn*32 + tx];
            float4 an = *reinterpret_cast<const float4*>(sAT + kn*AT_STRIDE + ty*4);
            acc[0][0]=fmaf(a.x,w.x,acc[0][0]); acc[0][1]=fmaf(a.x,w.y,acc[0][1]);
            acc[0][2]=fmaf(a.x,w.z,acc[0][2]); acc[0][3]=fmaf(a.x,w.w,acc[0][3]);
            acc[1][0]=fmaf(a.y,w.x,acc[1][0]); acc[1][1]=fmaf(a.y,w.y,acc[1][1]);
            acc[1][2]=fmaf(a.y,w.z,acc[1][2]); acc[1][3]=fmaf(a.y,w.w,acc[1][3]);
            acc[2][0]=fmaf(a.z,w.x,acc[2][0]); acc[2][1]=fmaf(a.z,w.y,acc[2][1]);
            acc[2][2]=fmaf(a.z,w.z,acc[2][2]); acc[2][3]=fmaf(a.z,w.w,acc[2][3]);
            acc[3][0]=fmaf(a.w,w.x,acc[3][0]); acc[3][1]=fmaf(a.w,w.y,acc[3][1]);
            acc[3][2]=fmaf(a.w,w.z,acc[3][2]); acc[3][3]=fmaf(a.w,w.w,acc[3][3]);
            w = wn; a = an;
        }
    }
    if (A2){
        __syncthreads();
        {
            const float4* W4 = (const float4*)W1;
            float4* sW4 = (float4*)sW;
            #pragma unroll
            for (int i = tid; i < HID*32; i += 512) sW4[i] = W4[i];
            const float4* A24 = (const float4*)A2;
            #pragma unroll
            for (int i = tid; i < 64*32; i += 512){
                int r = i >> 5, c4 = i & 31;
                float4 v = A24[(size_t)(row0+r)*32 + c4];
                int k0 = c4*4;
                sAT[(k0+0)*AT_STRIDE + r] = v.x;
                sAT[(k0+1)*AT_STRIDE + r] = v.y;
                sAT[(k0+2)*AT_STRIDE + r] = v.z;
                sAT[(k0+3)*AT_STRIDE + r] = v.w;
            }
        }
        __syncthreads();
        const float4* sW4 = (const float4*)sW;
        float4 w = sW4[tx];
        float4 a = *reinterpret_cast<const float4*>(sAT + ty*4);
        #pragma unroll 4
        for (int k = 0; k < HID; k++){
            int kn = (k+1) & 127;
            float4 wn = sW4[kn*32 + tx];
            float4 an = *reinterpret_cast<const float4*>(sAT + kn*AT_STRIDE + ty*4);
            acc[0][0]=fmaf(a.x,w.x,acc[0][0]); acc[0][1]=fmaf(a.x,w.y,acc[0][1]);
            acc[0][2]=fmaf(a.x,w.z,acc[0][2]); acc[0][3]=fmaf(a.x,w.w,acc[0][3]);
            acc[1][0]=fmaf(a.y,w.x,acc[1][0]); acc[1][1]=fmaf(a.y,w.y,acc[1][1]);
            acc[1][2]=fmaf(a.y,w.z,acc[1][2]); acc[1][3]=fmaf(a.y,w.w,acc[1][3]);
            acc[2][0]=fmaf(a.z,w.x,acc[2][0]); acc[2][1]=fmaf(a.z,w.y,acc[2][1]);
            acc[2][2]=fmaf(a.z,w.z,acc[2][2]); acc[2][3]=fmaf(a.z,w.w,acc[2][3]);
            acc[3][0]=fmaf(a.w,w.x,acc[3][0]); acc[3][1]=fmaf(a.w,w.y,acc[3][1]);
            acc[3][2]=fmaf(a.w,w.z,acc[3][2]); acc[3][3]=fmaf(a.w,w.w,acc[3][3]);
            w = wn; a = an;
        }
    }
    float bias[4] = {0.f,0.f,0.f,0.f};
    if (b0){
        #pragma unroll
        for (int j=0;j<4;j++) bias[j] += b0[col0+j];
    }
    if (b1){
        #pragma unroll
        for (int j=0;j<4;j++) bias[j] += b1[col0+j];
    }
    #pragma unroll
    for (int i=0;i<4;i++){
        #pragma unroll
        for (int j=0;j<4;j++){
            acc[i][j] += bias[j];
            if (act) acc[i][j] = tanhf(acc[i][j]);
        }
    }
    if (doLN){
        #pragma unroll
        for (int i=0;i<4;i++){
            float s = acc[i][0]+acc[i][1]+acc[i][2]+acc[i][3];
            #pragma unroll
            for (int o = 16; o > 0; o >>= 1) s += __shfl_xor_sync(0xffffffffu, s, o);
            float mean = s * (1.f/HID);
            float d0 = acc[i][0]-mean, d1 = acc[i][1]-mean,
                  d2 = acc[i][2]-mean, d3 = acc[i][3]-mean;
            float q = d0*d0 + d1*d1 + d2*d2 + d3*d3;
            #pragma unroll
            for (int o = 16; o > 0; o >>= 1) q += __shfl_xor_sync(0xffffffffu, q, o);
            float inv = 1.0f / sqrtf(q * (1.f/HID) + 1e-5f);
            acc[i][0] = d0*inv; acc[i][1] = d1*inv;
            acc[i][2] = d2*inv; acc[i][3] = d3*inv;
        }
    }
    #pragma unroll
    for (int i=0;i<4;i++){
        int r = row0 + ty*4 + i;
        float4 o;
        o.x = acc[i][0]; o.y = acc[i][1]; o.z = acc[i][2]; o.w = acc[i][3];
        *reinterpret_cast<float4*>(C + (size_t)r*HID + col0) = o;
    }
}

// ---------------- GAT: warp-per-(node,batch); half2 pair-dim layout ----------------
// lane owns dims {2L, 2L+1, 64+2L, 64+2L+1}; pair-a head = L>>3, pair-b head = 4+(L>>3).
__global__ void __launch_bounds__(256) k_gat(
    const __half* __restrict__ hp, const float* __restrict__ el,
    const float* __restrict__ er,
    const int* __restrict__ off, const int* __restrict__ srcs,
    float* __restrict__ kout,
    const float* __restrict__ yin, const float* __restrict__ k1,
    const float* __restrict__ k2, const float* __restrict__ k3, float dtc)
{
    const unsigned FULL = 0xffffffffu;
    __shared__ float s_wbuf[8*32*8];       // [warp][j][head]
    int n    = blockIdx.x;
    int b    = threadIdx.x >> 5;
    int lane = threadIdx.x & 31;
    int bn   = b*NN + n;
    float* swp = s_wbuf + b*(32*8);
    int ha = lane >> 3;        // head of pair-a (0..3)
    int hbid = 4 + ha;         // head of pair-b

    const __half* hb  = hp + (size_t)b*NN*HID;
    const float*  elb = el + (size_t)b*NN*HEADS;

    float erv[8];
    {
        float4 e0v = *reinterpret_cast<const float4*>(er + (size_t)bn*HEADS);
        float4 e1v = *reinterpret_cast<const float4*>(er + (size_t)bn*HEADS + 4);
        erv[0]=e0v.x; erv[1]=e0v.y; erv[2]=e0v.z; erv[3]=e0v.w;
        erv[4]=e1v.x; erv[5]=e1v.y; erv[6]=e1v.z; erv[7]=e1v.w;
    }

    int e0 = off[n], deg = off[n+1] - e0;

    float acc[4] = {0.f,0.f,0.f,0.f};
    float m[8], ssum[8];
    #pragma unroll
    for (int h=0;h<8;h++){ m[h] = -FLT_MAX; ssum[h] = 0.f; }

    for (int base = 0; base < deg; base += 32){
        int cnt = min(32, deg - base);
        float lg[8];
        if (lane < cnt){
            int sj = srcs[e0 + base + lane];
            float4 v0 = *reinterpret_cast<const float4*>(elb + (size_t)sj*HEADS);
            float4 v1 = *reinterpret_cast<const float4*>(elb + (size_t)sj*HEADS + 4);
            float t0;
            t0 = v0.x + erv[0]; lg[0] = (t0>=0.f)?t0:0.2f*t0;
            t0 = v0.y + erv[1]; lg[1] = (t0>=0.f)?t0:0.2f*t0;
            t0 = v0.z + erv[2]; lg[2] = (t0>=0.f)?t0:0.2f*t0;
            t0 = v0.w + erv[3]; lg[3] = (t0>=0.f)?t0:0.2f*t0;
            t0 = v1.x + erv[4]; lg[4] = (t0>=0.f)?t0:0.2f*t0;
            t0 = v1.y + erv[5]; lg[5] = (t0>=0.f)?t0:0.2f*t0;
            t0 = v1.z + erv[6]; lg[6] = (t0>=0.f)?t0:0.2f*t0;
            t0 = v1.w + erv[7]; lg[7] = (t0>=0.f)?t0:0.2f*t0;
        } else {
            #pragma unroll
            for (int h=0;h<8;h++) lg[h] = -FLT_MAX;
        }
        float nm[8];
        #pragma unroll
        for (int h=0;h<8;h++) nm[h] = lg[h];
        #pragma unroll
        for (int o = 16; o > 0; o >>= 1){
            #pragma unroll
            for (int h=0;h<8;h++)
                nm[h] = fmaxf(nm[h], __shfl_xor_sync(FULL, nm[h], o));
        }
        float w[8], sc[8];
        #pragma unroll
        for (int h=0;h<8;h++){
            float newm = fmaxf(m[h], nm[h]);
            sc[h] = (m[h] == -FLT_MAX) ? 0.f : __expf(m[h] - newm);
            m[h]  = newm;
            w[h]  = __expf(lg[h] - newm);
        }
        if (base > 0){
            float sa = sc[ha], sb = sc[hbid];
            acc[0] *= sa; acc[1] *= sa; acc[2] *= sb; acc[3] *= sb;
            #pragma unroll
            for (int h=0;h<8;h++) ssum[h] *= sc[h];
        }
        float cs[8];
        #pragma unroll
        for (int h=0;h<8;h++) cs[h] = w[h];
        #pragma unroll
        for (int o = 16; o > 0; o >>= 1){
            #pragma unroll
            for (int h=0;h<8;h++)
                cs[h] += __shfl_xor_sync(FULL, cs[h], o);
        }
        #pragma unroll
        for (int h=0;h<8;h++) ssum[h] += cs[h];
        // publish chunk weights + source ids to smem (per-warp), broadcast-read
        int sj_pub = (lane < cnt) ? srcs[e0 + base + lane] : 0;
        __syncwarp();
        *reinterpret_cast<float4*>(&swp[lane*8])   = make_float4(w[0],w[1],w[2],w[3]);
        *reinterpret_cast<float4*>(&swp[lane*8+4]) = make_float4(w[4],w[5],w[6],w[7]);
        __syncwarp();
        for (int j = 0; j < cnt; j++){
            int s = __shfl_sync(FULL, sj_pub, j);
            const __half* hr = hb + (size_t)s*HID + 2*lane;
            __half2 p0 = *reinterpret_cast<const __half2*>(hr);
            __half2 p1 = *reinterpret_cast<const __half2*>(hr + 64);
            float2 f0 = __half22float2(p0);
            float2 f1 = __half22float2(p1);
            float wa = swp[j*8 + ha];
            float wb = swp[j*8 + hbid];
            acc[0] = fmaf(wa, f0.x, acc[0]);
            acc[1] = fmaf(wa, f0.y, acc[1]);
            acc[2] = fmaf(wb, f1.x, acc[2]);
            acc[3] = fmaf(wb, f1.y, acc[3]);
        }
    }
    {
        float sa = ssum[ha] + 1e-16f;
        float sb = ssum[hbid] + 1e-16f;
        float kv0 = acc[0]/sa, kv1 = acc[1]/sa;
        float kv2 = acc[2]/sb, kv3 = acc[3]/sb;
        size_t o0 = (size_t)bn*HID + 2*lane;
        size_t o1 = o0 + 64;
        if (yin){
            float2 ya = *reinterpret_cast<const float2*>(yin + o0);
            float2 yb = *reinterpret_cast<const float2*>(yin + o1);
            float2 a1 = *reinterpret_cast<const float2*>(k1 + o0);
            float2 b1 = *reinterpret_cast<const float2*>(k1 + o1);
            float2 a2 = *reinterpret_cast<const float2*>(k2 + o0);
            float2 b2 = *reinterpret_cast<const float2*>(k2 + o1);
            float2 a3 = *reinterpret_cast<const float2*>(k3 + o0);
            float2 b3 = *reinterpret_cast<const float2*>(k3 + o1);
            float2 ra, rb;
            ra.x = ya.x + dtc*(a1.x + 2.f*a2.x + 2.f*a3.x + kv0);
            ra.y = ya.y + dtc*(a1.y + 2.f*a2.y + 2.f*a3.y + kv1);
            rb.x = yb.x + dtc*(b1.x + 2.f*b2.x + 2.f*b3.x + kv2);
            rb.y = yb.y + dtc*(b1.y + 2.f*b2.y + 2.f*b3.y + kv3);
            *reinterpret_cast<float2*>(kout + o0) = ra;
            *reinterpret_cast<float2*>(kout + o1) = rb;
        } else {
            *reinterpret_cast<float2*>(kout + o0) = make_float2(kv0, kv1);
            *reinterpret_cast<float2*>(kout + o1) = make_float2(kv2, kv3);
        }
    }
}

// ---------------- LayerNorm (idx==0 only) ----------------
__global__ void __launch_bounds__(128) k_ln(const float* __restrict__ s, float* __restrict__ d){
    int row = blockIdx.x;
    int t = threadIdx.x;
    __shared__ float sh[4];
    float v = s[(size_t)row*HID + t];

    float a = v;
    #pragma unroll
    for (int o = 16; o > 0; o >>= 1) a += __shfl_xor_sync(0xffffffffu, a, o);
    if ((t & 31) == 0) sh[t >> 5] = a;
    __syncthreads();
    float mean = (sh[0]+sh[1]+sh[2]+sh[3]) * (1.f/HID);

    float dv = v - mean;
    float q = dv*dv;
    __syncthreads();
    #pragma unroll
    for (int o = 16; o > 0; o >>= 1) q += __shfl_xor_sync(0xffffffffu, q, o);
    if ((t & 31) == 0) sh[t >> 5] = q;
    __syncthreads();
    float var = (sh[0]+sh[1]+sh[2]+sh[3]) * (1.f/HID);

    d[(size_t)row*HID + t] = dv / sqrtf(var + 1e-5f);
}

// ---------------- launch ----------------
extern "C" void kernel_launch(void* const* d_in, const int* in_sizes, int n_in,
                              void* d_out, int out_size)
{
    const float* inputs = (const float*)d_in[0];
    const int*   src    = (const int*)  d_in[1];
    const int*   dst    = (const int*)  d_in[2];
    const float* w_in   = (const float*)d_in[3];
    const float* b_in   = (const float*)d_in[4];
    const float* w_gat  = (const float*)d_in[5];
    const float* a_l    = (const float*)d_in[6];
    const float* a_r    = (const float*)d_in[7];
    const float* w_W    = (const float*)d_in[8];
    const float* b_W    = (const float*)d_in[9];
    const float* w_U    = (const float*)d_in[10];
    const float* b_U    = (const float*)d_in[11];
    const float* w_o1   = (const float*)d_in[12];
    const float* b_o1   = (const float*)d_in[13];
    const float* w_o2   = (const float*)d_in[14];
    const float* b_o2   = (const float*)d_in[15];
    float* out = (float*)d_out;

    float *hin, *y, *k1, *k2, *k3, *tmp, *el, *er;
    __half *hp;
    unsigned *wh;
    int *cnt, *cur, *off, *eidx, *srcs;
    cudaGetSymbolAddress((void**)&hin, g_hin);
    cudaGetSymbolAddress((void**)&y,   g_y);
    cudaGetSymbolAddress((void**)&hp,  g_hp);
    cudaGetSymbolAddress((void**)&k1,  g_k1);
    cudaGetSymbolAddress((void**)&k2,  g_k2);
    cudaGetSymbolAddress((void**)&k3,  g_k3);
    cudaGetSymbolAddress((void**)&tmp, g_tmp);
    cudaGetSymbolAddress((void**)&el,  g_el);
    cudaGetSymbolAddress((void**)&er,  g_er);
    cudaGetSymbolAddress((void**)&wh,  g_wh);
    cudaGetSymbolAddress((void**)&cnt, g_cnt);
    cudaGetSymbolAddress((void**)&cur, g_cur);
    cudaGetSymbolAddress((void**)&off, g_off);
    cudaGetSymbolAddress((void**)&eidx,g_eidx);
    cudaGetSymbolAddress((void**)&srcs,g_srcs);

    const float* F0 = (const float*)0;

    static bool attr_set = false;
    if (!attr_set){
        cudaFuncSetAttribute(k_gemm,   cudaFuncAttributeMaxDynamicSharedMemorySize, GEMM_SMEM);
        cudaFuncSetAttribute(k_gemm_h, cudaFuncAttributeMaxDynamicSharedMemorySize, HMMA_SMEM);
        attr_set = true;
    }

    const float dt  = 0.25f;
    const float dtc = dt / 6.0f;

    // prelude
    k_init      <<<B*SEQ*NN, HID>>>(inputs, w_in, b_in, hin, y, cnt, cur);
    k_wsplit    <<<(HID*HID/2+255)/256, 256>>>(w_gat, wh);
    k_csr_count <<<(E+255)/256, 256>>>(dst, cnt);
    k_csr_scan  <<<1, 1024>>>(cnt, off);

    // first RK4 stage-1 GEMM (does not need CSR)
    k_gemm_h<<<125,512,HMMA_SMEM>>>(y, F0, 0.f, wh, hp, el, er, a_l, a_r);

    k_csr_fill  <<<(E+255)/256, 256>>>(dst, off, cur, eidx);
    k_csr_sort  <<<NN, 32>>>(off, eidx);
    k_csr_gather<<<(E+255)/256, 256>>>(eidx, src, srcs);

    for (int idx = 0; idx < SEQ; idx++){
        for (int s = 0; s < 4; s++){
            if (!(idx == 0 && s == 0)){
                k_gemm_h<<<125,512,HMMA_SMEM>>>(y, F0, 0.f, wh, hp, el, er, a_l, a_r);
            }
            k_gat <<<NN,256>>>(hp, el, er, off, srcs, k1, F0,F0,F0,F0, 0.f);
            k_gemm_h<<<125,512,HMMA_SMEM>>>(y, k1, 0.5f*dt, wh, hp, el, er, a_l, a_r);
            k_gat <<<NN,256>>>(hp, el, er, off, srcs, k2, F0,F0,F0,F0, 0.f);
            k_gemm_h<<<125,512,HMMA_SMEM>>>(y, k2, 0.5f*dt, wh, hp, el, er, a_l, a_r);
            k_gat <<<NN,256>>>(hp, el, er, off, srcs, k3, F0,F0,F0,F0, 0.f);
            k_gemm_h<<<125,512,HMMA_SMEM>>>(y, k3, dt, wh, hp, el, er, a_l, a_r);
            k_gat <<<NN,256>>>(hp, el, er, off, srcs, y, y, k1, k2, k3, dtc);
        }
        if (idx > 0){
            // y = LN(tanh(y@w_W + h[idx]@w_U + b_W + b_U)) — LN fused (FFMA path)
            const float* hidx = hin + (size_t)idx * M_ROWS * HID;
            k_gemm<<<125,512,GEMM_SMEM>>>(y, w_W, hidx, w_U, b_W, b_U, y, 1, 1);
        } else {
            k_ln  <<<M_ROWS,128>>>(y, y);
        }
    }

    // out = tanh(y@w_o1 + b_o1) @ w_o2 + b_o2  (FFMA path)
    k_gemm<<<125,512,GEMM_SMEM>>>(y,   w_o1, F0, F0, b_o1, F0, tmp, 1, 0);
    k_gemm<<<125,512,GEMM_SMEM>>>(tmp, w_o2, F0, F0, b_o2, F0, out, 0, 0);
}

// round 17
// speedup vs baseline: 1.3683x; 1.3683x over previous
#include <cuda_runtime.h>
#include <cuda_fp16.h>
#include <math.h>
#include <float.h>
#include <stdint.h>

#define B 8
#define SEQ 12
#define NN 1000
#define E 16000
#define HID 128
#define HEADS 8
#define DH 16
#define M_ROWS (B*NN)          /* 8000 */

#define AT_STRIDE 68
#define GEMM_SMEM (HID*HID*4 + HID*AT_STRIDE*4)   /* FFMA gemm */

/* fp16-mma gemm smem (uint32 words), stride 68 words per row */
#define HS 68
#define A_H_OFF 0
#define A_L_OFF (64*HS)
#define B_H_OFF (2*64*HS)
#define HMMA_SMEM ((2*64*HS + 128*HS)*4)   /* 69632 B */

// ---------------- static device scratch ----------------
__device__ float    g_hin[(size_t)SEQ*B*NN*HID];
__device__ float    g_y  [(size_t)M_ROWS*HID];
__device__ __half   g_hp [(size_t)M_ROWS*HID];
__device__ float    g_k1 [(size_t)M_ROWS*HID];
__device__ float    g_k2 [(size_t)M_ROWS*HID];
__device__ float    g_k3 [(size_t)M_ROWS*HID];
__device__ float    g_tmp[(size_t)M_ROWS*HID];
__device__ float    g_el [(size_t)M_ROWS*HEADS];
__device__ float    g_er [(size_t)M_ROWS*HEADS];
__device__ unsigned g_wh [HID*HID/2];   /* W^T fp16 hi: [n][kword] */
__device__ int      g_cnt[NN];
__device__ int      g_cur[NN];
__device__ int      g_off[NN+1];
__device__ int      g_eidx[E];
__device__ int      g_srcs[E];

// ---------------- helpers ----------------
__device__ __forceinline__ unsigned packh2(float a, float b){
    __half2 t = __floats2half2_rn(a, b);
    unsigned u; memcpy(&u, &t, 4); return u;
}
__device__ __forceinline__ float h_res(float x){
    return x - __half2float(__float2half_rn(x));
}
#define HMMA16(c, a0,a1,a2,a3, b0,b1) \
    asm volatile("mma.sync.aligned.m16n8k16.row.col.f32.f16.f16.f32 " \
        "{%0,%1,%2,%3}, {%4,%5,%6,%7}, {%8,%9}, {%0,%1,%2,%3};" \
        : "+f"((c)[0]), "+f"((c)[1]), "+f"((c)[2]), "+f"((c)[3]) \
        : "r"(a0), "r"(a1), "r"(a2), "r"(a3), "r"(b0), "r"(b1))

// ---------------- fused init: inproj + y=h[:,0] + CSR zero ----------------
__global__ void k_init(const float* __restrict__ inp, const float* __restrict__ w_in,
                       const float* __restrict__ b_in, float* __restrict__ hin,
                       float* __restrict__ y, int* cnt, int* cur){
    int row = blockIdx.x;
    int t = threadIdx.x;
    if (blockIdx.x < 8){
        int q = blockIdx.x*128 + t;
        if (q < NN){ cnt[q] = 0; cur[q] = 0; }
    }
    int b = row / (SEQ*NN);
    int s = (row / NN) % SEQ;
    int n = row % NN;
    float x0 = inp[(size_t)row*2 + 0];
    float x1 = inp[(size_t)row*2 + 1];
    float v = fmaf(x0, w_in[t], fmaf(x1, w_in[HID+t], b_in[t]));
    hin[(((size_t)s*B + b)*NN + n)*HID + t] = v;
    if (s == 0) y[((size_t)b*NN + n)*HID + t] = v;
}

// ---------------- W^T fp16 split: g_wh[n*64 + kword] ----------------
__global__ void k_wsplit(const float* __restrict__ w, unsigned* wh){
    int i = blockIdx.x*256 + threadIdx.x;
    if (i >= HID*HID/2) return;
    int n = i >> 6, kw = i & 63;
    int k0 = kw*2;
    wh[i] = packh2(w[(size_t)k0*HID + n], w[(size_t)(k0+1)*HID + n]);
}

// ---------------- CSR construction (deterministic) ----------------
__global__ void k_csr_count(const int* __restrict__ dst, int* cnt){
    int e = blockIdx.x*blockDim.x + threadIdx.x;
    if (e < E) atomicAdd(&cnt[dst[e]], 1);
}
__global__ void k_csr_scan(const int* __restrict__ cnt, int* off){
    __shared__ int s[1024];
    int t = threadIdx.x;
    s[t] = (t < NN) ? cnt[t] : 0;
    __syncthreads();
    #pragma unroll
    for (int o = 1; o < 1024; o <<= 1){
        int v = (t >= o) ? s[t-o] : 0;
        __syncthreads();
        s[t] += v;
        __syncthreads();
    }
    if (t == 0) off[0] = 0;
    if (t < NN) off[t+1] = s[t];
}
__global__ void k_csr_fill(const int* __restrict__ dst, const int* __restrict__ off,
                           int* cur, int* eidx){
    int e = blockIdx.x*blockDim.x + threadIdx.x;
    if (e < E){
        int d = dst[e];
        int p = atomicAdd(&cur[d], 1);
        eidx[off[d] + p] = e;
    }
}
// sort each node's edge list (deterministic) + gather source ids
__global__ void k_csr_sort(const int* __restrict__ off, int* eidx,
                           const int* __restrict__ src, int* __restrict__ srcs){
    if (threadIdx.x != 0) return;
    int n = blockIdx.x;
    int a = off[n], b = off[n+1];
    for (int i = a+1; i < b; i++){
        int v = eidx[i]; int j = i-1;
        while (j >= a && eidx[j] > v){ eidx[j+1] = eidx[j]; j--; }
        eidx[j+1] = v;
    }
    for (int i = a; i < b; i++) srcs[i] = src[eidx[i]];
}

// ========== fp16 HMMA GEMM (GAT path): hp(fp16) = (A0 + c1*A1) @ W_gat ==========
// 2-term split: Ah*Wh + Al*Wh (W effectively fp16). 64x128 tile, grid 125,
// 512 threads = 16 warps, 16x32 out each via m16n8k16.
__global__ void __launch_bounds__(512) k_gemm_h(
    const float* __restrict__ A0, const float* __restrict__ A1, float c1,
    const unsigned* __restrict__ WH,
    __half* __restrict__ Ch,
    float* __restrict__ el, float* __restrict__ er,
    const float* __restrict__ a_l, const float* __restrict__ a_r)
{
    extern __shared__ unsigned hsm[];
    unsigned* sAh = hsm + A_H_OFF;   // [64][HS]
    unsigned* sAl = hsm + A_L_OFF;
    unsigned* sBh = hsm + B_H_OFF;   // [128][HS]

    int tid  = threadIdx.x;
    int lane = tid & 31, w = tid >> 5;
    int row0 = blockIdx.x * 64;
    int mrow = (w & 3) * 16;
    int ncol = (w >> 2) * 32;
    int g = lane >> 2;        // 0..7
    int t = lane & 3;         // 0..3

    // ---- stage B hi (copy, row-padded) ----
    {
        const uint4* H4 = (const uint4*)WH;
        #pragma unroll
        for (int i = tid; i < 2048; i += 512){
            int n = i >> 4, kw = (i & 15) * 4;
            *reinterpret_cast<uint4*>(&sBh[n*HS + kw]) = H4[i];
        }
    }
    // ---- stage A hi/lo (fused axpy + fp16 split) ----
    {
        const float4* A04 = (const float4*)A0;
        const float4* A14 = (const float4*)A1;
        #pragma unroll
        for (int i = tid; i < 64*32; i += 512){
            int r = i >> 5, c4 = i & 31;
            float4 v = A04[(size_t)(row0+r)*32 + c4];
            if (A1){
                float4 u = A14[(size_t)(row0+r)*32 + c4];
                v.x = fmaf(c1,u.x,v.x); v.y = fmaf(c1,u.y,v.y);
                v.z = fmaf(c1,u.z,v.z); v.w = fmaf(c1,u.w,v.w);
            }
            int kw = c4*2;
            sAh[r*HS + kw]     = packh2(v.x, v.y);
            sAh[r*HS + kw + 1] = packh2(v.z, v.w);
            sAl[r*HS + kw]     = packh2(h_res(v.x), h_res(v.y));
            sAl[r*HS + kw + 1] = packh2(h_res(v.z), h_res(v.w));
        }
    }
    __syncthreads();

    float acc[4][4];
    #pragma unroll
    for (int i=0;i<4;i++)
        #pragma unroll
        for (int j=0;j<4;j++) acc[i][j] = 0.f;

    const unsigned* pAh1 = sAh + (mrow + g)*HS;
    const unsigned* pAh2 = pAh1 + 8*HS;
    const unsigned* pAl1 = sAl + (mrow + g)*HS;
    const unsigned* pAl2 = pAl1 + 8*HS;

    #pragma unroll
    for (int ks = 0; ks < 8; ks++){
        int kw = ks*8 + t;
        unsigned ah0 = pAh1[kw], ah1 = pAh2[kw], ah2 = pAh1[kw+4], ah3 = pAh2[kw+4];
        unsigned al0 = pAl1[kw], al1 = pAl2[kw], al2 = pAl1[kw+4], al3 = pAl2[kw+4];
        #pragma unroll
        for (int nt = 0; nt < 4; nt++){
            int bi = (ncol + nt*8 + g)*HS + kw;
            unsigned bh0 = sBh[bi], bh1 = sBh[bi+4];
            HMMA16(acc[nt], ah0,ah1,ah2,ah3, bh0,bh1);
            HMMA16(acc[nt], al0,al1,al2,al3, bh0,bh1);
        }
    }

    // ---- store hp (fp16) ----
    {
        size_t r1 = row0 + mrow + g;
        #pragma unroll
        for (int nt=0; nt<4; nt++){
            int col = ncol + nt*8 + t*2;
            __half2 p0 = __floats2half2_rn(acc[nt][0], acc[nt][1]);
            __half2 p1 = __floats2half2_rn(acc[nt][2], acc[nt][3]);
            *reinterpret_cast<__half2*>(Ch + r1*HID + col)     = p0;
            *reinterpret_cast<__half2*>(Ch + (r1+8)*HID + col) = p1;
        }
    }
    // ---- el/er epilogue (verified fragment layout) ----
    {
        int h0 = ncol >> 4;
        float pl[2][2] = {{0.f,0.f},{0.f,0.f}};
        float pr[2][2] = {{0.f,0.f},{0.f,0.f}};
        #pragma unroll
        for (int nt=0; nt<4; nt++){
            int hp_ = nt >> 1;
            int d   = (nt & 1)*8 + t*2;
            int h   = h0 + hp_;
            float l0 = a_l[h*DH + d],  l1 = a_l[h*DH + d + 1];
            float r0 = a_r[h*DH + d],  r1 = a_r[h*DH + d + 1];
            pl[hp_][0] += acc[nt][0]*l0 + acc[nt][1]*l1;
            pl[hp_][1] += acc[nt][2]*l0 + acc[nt][3]*l1;
            pr[hp_][0] += acc[nt][0]*r0 + acc[nt][1]*r1;
            pr[hp_][1] += acc[nt][2]*r0 + acc[nt][3]*r1;
        }
        #pragma unroll
        for (int hp_=0; hp_<2; hp_++){
            #pragma unroll
            for (int rh=0; rh<2; rh++){
                pl[hp_][rh] += __shfl_xor_sync(0xffffffffu, pl[hp_][rh], 1);
                pl[hp_][rh] += __shfl_xor_sync(0xffffffffu, pl[hp_][rh], 2);
                pr[hp_][rh] += __shfl_xor_sync(0xffffffffu, pr[hp_][rh], 1);
                pr[hp_][rh] += __shfl_xor_sync(0xffffffffu, pr[hp_][rh], 2);
            }
        }
        if (t == 0){
            int r1 = row0 + mrow + g;
            el[(size_t)r1*HEADS + h0]       = pl[0][0];
            el[(size_t)(r1+8)*HEADS + h0]   = pl[0][1];
            el[(size_t)r1*HEADS + h0+1]     = pl[1][0];
            el[(size_t)(r1+8)*HEADS + h0+1] = pl[1][1];
            er[(size_t)r1*HEADS + h0]       = pr[0][0];
            er[(size_t)(r1+8)*HEADS + h0]   = pr[0][1];
            er[(size_t)r1*HEADS + h0+1]     = pr[1][0];
            er[(size_t)(r1+8)*HEADS + h0+1] = pr[1][1];
        }
    }
}

// ---------------- FFMA GEMM (tanh/LN + head path; proven) ----------------
__global__ void __launch_bounds__(512) k_gemm(
    const float* __restrict__ A0,
    const float* __restrict__ W0,
    const float* __restrict__ A2, const float* __restrict__ W1,
    const float* __restrict__ b0, const float* __restrict__ b1,
    float* __restrict__ C, int act, int doLN)
{
    extern __shared__ float fsm[];
    float* sW  = fsm;
    float* sAT = fsm + HID*HID;

    int row0 = blockIdx.x * 64;
    int tid = threadIdx.x;
    int tx = tid & 31, ty = tid >> 5;
    int col0 = tx * 4;

    float acc[4][4];
    #pragma unroll
    for (int i=0;i<4;i++)
        #pragma unroll
        for (int j=0;j<4;j++) acc[i][j] = 0.f;

    {
        const float4* W4 = (const float4*)W0;
        float4* sW4 = (float4*)sW;
        #pragma unroll
        for (int i = tid; i < HID*32; i += 512) sW4[i] = W4[i];
        const float4* A04 = (const float4*)A0;
        #pragma unroll
        for (int i = tid; i < 64*32; i += 512){
            int r = i >> 5, c4 = i & 31;
            float4 v = A04[(size_t)(row0+r)*32 + c4];
            int k0 = c4*4;
            sAT[(k0+0)*AT_STRIDE + r] = v.x;
            sAT[(k0+1)*AT_STRIDE + r] = v.y;
            sAT[(k0+2)*AT_STRIDE + r] = v.z;
            sAT[(k0+3)*AT_STRIDE + r] = v.w;
        }
    }
    __syncthreads();
    {
        const float4* sW4 = (const float4*)sW;
        float4 w = sW4[tx];
        float4 a = *reinterpret_cast<const float4*>(sAT + ty*4);
        #pragma unroll 4
        for (int k = 0; k < HID; k++){
            int kn = (k+1) & 127;
            float4 wn = sW4[kn*32 + tx];
            float4 an = *reinterpret_cast<const float4*>(sAT + kn*AT_STRIDE + ty*4);
            acc[0][0]=fmaf(a.x,w.x,acc[0][0]); acc[0][1]=fmaf(a.x,w.y,acc[0][1]);
            acc[0][2]=fmaf(a.x,w.z,acc[0][2]); acc[0][3]=fmaf(a.x,w.w,acc[0][3]);
            acc[1][0]=fmaf(a.y,w.x,acc[1][0]); acc[1][1]=fmaf(a.y,w.y,acc[1][1]);
            acc[1][2]=fmaf(a.y,w.z,acc[1][2]); acc[1][3]=fmaf(a.y,w.w,acc[1][3]);
            acc[2][0]=fmaf(a.z,w.x,acc[2][0]); acc[2][1]=fmaf(a.z,w.y,acc[2][1]);
            acc[2][2]=fmaf(a.z,w.z,acc[2][2]); acc[2][3]=fmaf(a.z,w.w,acc[2][3]);
            acc[3][0]=fmaf(a.w,w.x,acc[3][0]); acc[3][1]=fmaf(a.w,w.y,acc[3][1]);
            acc[3][2]=fmaf(a.w,w.z,acc[3][2]); acc[3][3]=fmaf(a.w,w.w,acc[3][3]);
            w = wn; a = an;
        }
    }
    if (A2){
        __syncthreads();
        {
            const float4* W4 = (const float4*)W1;
            float4* sW4 = (float4*)sW;
            #pragma unroll
            for (int i = tid; i < HID*32; i += 512) sW4[i] = W4[i];
            const float4* A24 = (const float4*)A2;
            #pragma unroll
            for (int i = tid; i < 64*32; i += 512){
                int r = i >> 5, c4 = i & 31;
                float4 v = A24[(size_t)(row0+r)*32 + c4];
                int k0 = c4*4;
                sAT[(k0+0)*AT_STRIDE + r] = v.x;
                sAT[(k0+1)*AT_STRIDE + r] = v.y;
                sAT[(k0+2)*AT_STRIDE + r] = v.z;
                sAT[(k0+3)*AT_STRIDE + r] = v.w;
            }
        }
        __syncthreads();
        const float4* sW4 = (const float4*)sW;
        float4 w = sW4[tx];
        float4 a = *reinterpret_cast<const float4*>(sAT + ty*4);
        #pragma unroll 4
        for (int k = 0; k < HID; k++){
            int kn = (k+1) & 127;
            float4 wn = sW4[kn*32 + tx];
            float4 an = *reinterpret_cast<const float4*>(sAT + kn*AT_STRIDE + ty*4);
            acc[0][0]=fmaf(a.x,w.x,acc[0][0]); acc[0][1]=fmaf(a.x,w.y,acc[0][1]);
            acc[0][2]=fmaf(a.x,w.z,acc[0][2]); acc[0][3]=fmaf(a.x,w.w,acc[0][3]);
            acc[1][0]=fmaf(a.y,w.x,acc[1][0]); acc[1][1]=fmaf(a.y,w.y,acc[1][1]);
            acc[1][2]=fmaf(a.y,w.z,acc[1][2]); acc[1][3]=fmaf(a.y,w.w,acc[1][3]);
            acc[2][0]=fmaf(a.z,w.x,acc[2][0]); acc[2][1]=fmaf(a.z,w.y,acc[2][1]);
            acc[2][2]=fmaf(a.z,w.z,acc[2][2]); acc[2][3]=fmaf(a.z,w.w,acc[2][3]);
            acc[3][0]=fmaf(a.w,w.x,acc[3][0]); acc[3][1]=fmaf(a.w,w.y,acc[3][1]);
            acc[3][2]=fmaf(a.w,w.z,acc[3][2]); acc[3][3]=fmaf(a.w,w.w,acc[3][3]);
            w = wn; a = an;
        }
    }
    float bias[4] = {0.f,0.f,0.f,0.f};
    if (b0){
        #pragma unroll
        for (int j=0;j<4;j++) bias[j] += b0[col0+j];
    }
    if (b1){
        #pragma unroll
        for (int j=0;j<4;j++) bias[j] += b1[col0+j];
    }
    #pragma unroll
    for (int i=0;i<4;i++){
        #pragma unroll
        for (int j=0;j<4;j++){
            acc[i][j] += bias[j];
            if (act) acc[i][j] = tanhf(acc[i][j]);
        }
    }
    if (doLN){
        #pragma unroll
        for (int i=0;i<4;i++){
            float s = acc[i][0]+acc[i][1]+acc[i][2]+acc[i][3];
            #pragma unroll
            for (int o = 16; o > 0; o >>= 1) s += __shfl_xor_sync(0xffffffffu, s, o);
            float mean = s * (1.f/HID);
            float d0 = acc[i][0]-mean, d1 = acc[i][1]-mean,
                  d2 = acc[i][2]-mean, d3 = acc[i][3]-mean;
            float q = d0*d0 + d1*d1 + d2*d2 + d3*d3;
            #pragma unroll
            for (int o = 16; o > 0; o >>= 1) q += __shfl_xor_sync(0xffffffffu, q, o);
            float inv = 1.0f / sqrtf(q * (1.f/HID) + 1e-5f);
            acc[i][0] = d0*inv; acc[i][1] = d1*inv;
            acc[i][2] = d2*inv; acc[i][3] = d3*inv;
        }
    }
    #pragma unroll
    for (int i=0;i<4;i++){
        int r = row0 + ty*4 + i;
        float4 o;
        o.x = acc[i][0]; o.y = acc[i][1]; o.z = acc[i][2]; o.w = acc[i][3];
        *reinterpret_cast<float4*>(C + (size_t)r*HID + col0) = o;
    }
}

// ---------------- GAT: warp-per-(node,batch); smem weight buffer (R15-proven) ----
__global__ void __launch_bounds__(256) k_gat(
    const __half* __restrict__ hp, const float* __restrict__ el,
    const float* __restrict__ er,
    const int* __restrict__ off, const int* __restrict__ srcs,
    float* __restrict__ kout,
    const float* __restrict__ yin, const float* __restrict__ k1,
    const float* __restrict__ k2, const float* __restrict__ k3, float dtc)
{
    const unsigned FULL = 0xffffffffu;
    __shared__ float s_wbuf[8*32*8];       // [warp][j][head]
    int n    = blockIdx.x;
    int b    = threadIdx.x >> 5;
    int lane = threadIdx.x & 31;
    int bn   = b*NN + n;
    float* swp = s_wbuf + b*(32*8);
    int hi = lane >> 4;                    // 0 or 1: even/odd head of pair

    const __half* hb  = hp + (size_t)b*NN*HID;
    const float*  elb = el + (size_t)b*NN*HEADS;

    float erv[8];
    {
        float4 e0v = *reinterpret_cast<const float4*>(er + (size_t)bn*HEADS);
        float4 e1v = *reinterpret_cast<const float4*>(er + (size_t)bn*HEADS + 4);
        erv[0]=e0v.x; erv[1]=e0v.y; erv[2]=e0v.z; erv[3]=e0v.w;
        erv[4]=e1v.x; erv[5]=e1v.y; erv[6]=e1v.z; erv[7]=e1v.w;
    }

    int e0 = off[n], deg = off[n+1] - e0;

    float acc[4] = {0.f,0.f,0.f,0.f};
    float m[8], ssum[8];
    #pragma unroll
    for (int h=0;h<8;h++){ m[h] = -FLT_MAX; ssum[h] = 0.f; }

    for (int base = 0; base < deg; base += 32){
        int cnt = min(32, deg - base);
        int sj = 0;
        float lg[8];
        if (lane < cnt){
            sj = srcs[e0 + base + lane];
            float4 v0 = *reinterpret_cast<const float4*>(elb + (size_t)sj*HEADS);
            float4 v1 = *reinterpret_cast<const float4*>(elb + (size_t)sj*HEADS + 4);
            float t0;
            t0 = v0.x + erv[0]; lg[0] = (t0>=0.f)?t0:0.2f*t0;
            t0 = v0.y + erv[1]; lg[1] = (t0>=0.f)?t0:0.2f*t0;
            t0 = v0.z + erv[2]; lg[2] = (t0>=0.f)?t0:0.2f*t0;
            t0 = v0.w + erv[3]; lg[3] = (t0>=0.f)?t0:0.2f*t0;
            t0 = v1.x + erv[4]; lg[4] = (t0>=0.f)?t0:0.2f*t0;
            t0 = v1.y + erv[5]; lg[5] = (t0>=0.f)?t0:0.2f*t0;
            t0 = v1.z + erv[6]; lg[6] = (t0>=0.f)?t0:0.2f*t0;
            t0 = v1.w + erv[7]; lg[7] = (t0>=0.f)?t0:0.2f*t0;
        } else {
            #pragma unroll
            for (int h=0;h<8;h++) lg[h] = -FLT_MAX;
        }
        float nm[8];
        #pragma unroll
        for (int h=0;h<8;h++) nm[h] = lg[h];
        #pragma unroll
        for (int o = 16; o > 0; o >>= 1){
            #pragma unroll
            for (int h=0;h<8;h++)
                nm[h] = fmaxf(nm[h], __shfl_xor_sync(FULL, nm[h], o));
        }
        float w[8], sc[8];
        #pragma unroll
        for (int h=0;h<8;h++){
            float newm = fmaxf(m[h], nm[h]);
            sc[h] = (m[h] == -FLT_MAX) ? 0.f : __expf(m[h] - newm);
            m[h]  = newm;
            w[h]  = __expf(lg[h] - newm);
        }
        if (base > 0){
            #pragma unroll
            for (int g=0;g<4;g++){
                float s01 = (lane < 16) ? sc[2*g] : sc[2*g+1];
                acc[g] *= s01;
            }
            #pragma unroll
            for (int h=0;h<8;h++) ssum[h] *= sc[h];
        }
        float cs[8];
        #pragma unroll
        for (int h=0;h<8;h++) cs[h] = w[h];
        #pragma unroll
        for (int o = 16; o > 0; o >>= 1){
            #pragma unroll
            for (int h=0;h<8;h++)
                cs[h] += __shfl_xor_sync(FULL, cs[h], o);
        }
        #pragma unroll
        for (int h=0;h<8;h++) ssum[h] += cs[h];
        // publish chunk weights to smem (per-warp tile), then broadcast-read
        __syncwarp();
        *reinterpret_cast<float4*>(&swp[lane*8])   = make_float4(w[0],w[1],w[2],w[3]);
        *reinterpret_cast<float4*>(&swp[lane*8+4]) = make_float4(w[4],w[5],w[6],w[7]);
        __syncwarp();
        for (int j = 0; j < cnt; j++){
            int s = __shfl_sync(FULL, sj, j);
            const __half* hr = hb + (size_t)s*HID;
            const float*  wj = swp + j*8 + hi;
            float h0 = __half2float(hr[lane]);
            float h1 = __half2float(hr[lane + 32]);
            float h2 = __half2float(hr[lane + 64]);
            float h3 = __half2float(hr[lane + 96]);
            acc[0] = fmaf(wj[0], h0, acc[0]);
            acc[1] = fmaf(wj[2], h1, acc[1]);
            acc[2] = fmaf(wj[4], h2, acc[2]);
            acc[3] = fmaf(wj[6], h3, acc[3]);
        }
    }
    #pragma unroll
    for (int g=0;g<4;g++){
        float s = ((lane < 16) ? ssum[2*g] : ssum[2*g+1]) + 1e-16f;
        float kv = acc[g] / s;
        size_t o = (size_t)bn*HID + lane + 32*g;
        if (yin){
            kout[o] = yin[o] + dtc*(k1[o] + 2.f*k2[o] + 2.f*k3[o] + kv);
        } else {
            kout[o] = kv;
        }
    }
}

// ---------------- LayerNorm (idx==0 only) ----------------
__global__ void __launch_bounds__(128) k_ln(const float* __restrict__ s, float* __restrict__ d){
    int row = blockIdx.x;
    int t = threadIdx.x;
    __shared__ float sh[4];
    float v = s[(size_t)row*HID + t];

    float a = v;
    #pragma unroll
    for (int o = 16; o > 0; o >>= 1) a += __shfl_xor_sync(0xffffffffu, a, o);
    if ((t & 31) == 0) sh[t >> 5] = a;
    __syncthreads();
    float mean = (sh[0]+sh[1]+sh[2]+sh[3]) * (1.f/HID);

    float dv = v - mean;
    float q = dv*dv;
    __syncthreads();
    #pragma unroll
    for (int o = 16; o > 0; o >>= 1) q += __shfl_xor_sync(0xffffffffu, q, o);
    if ((t & 31) == 0) sh[t >> 5] = q;
    __syncthreads();
    float var = (sh[0]+sh[1]+sh[2]+sh[3]) * (1.f/HID);

    d[(size_t)row*HID + t] = dv / sqrtf(var + 1e-5f);
}

// ---------------- launch ----------------
extern "C" void kernel_launch(void* const* d_in, const int* in_sizes, int n_in,
                              void* d_out, int out_size)
{
    const float* inputs = (const float*)d_in[0];
    const int*   src    = (const int*)  d_in[1];
    const int*   dst    = (const int*)  d_in[2];
    const float* w_in   = (const float*)d_in[3];
    const float* b_in   = (const float*)d_in[4];
    const float* w_gat  = (const float*)d_in[5];
    const float* a_l    = (const float*)d_in[6];
    const float* a_r    = (const float*)d_in[7];
    const float* w_W    = (const float*)d_in[8];
    const float* b_W    = (const float*)d_in[9];
    const float* w_U    = (const float*)d_in[10];
    const float* b_U    = (const float*)d_in[11];
    const float* w_o1   = (const float*)d_in[12];
    const float* b_o1   = (const float*)d_in[13];
    const float* w_o2   = (const float*)d_in[14];
    const float* b_o2   = (const float*)d_in[15];
    float* out = (float*)d_out;

    float *hin, *y, *k1, *k2, *k3, *tmp, *el, *er;
    __half *hp;
    unsigned *wh;
    int *cnt, *cur, *off, *eidx, *srcs;
    cudaGetSymbolAddress((void**)&hin, g_hin);
    cudaGetSymbolAddress((void**)&y,   g_y);
    cudaGetSymbolAddress((void**)&hp,  g_hp);
    cudaGetSymbolAddress((void**)&k1,  g_k1);
    cudaGetSymbolAddress((void**)&k2,  g_k2);
    cudaGetSymbolAddress((void**)&k3,  g_k3);
    cudaGetSymbolAddress((void**)&tmp, g_tmp);
    cudaGetSymbolAddress((void**)&el,  g_el);
    cudaGetSymbolAddress((void**)&er,  g_er);
    cudaGetSymbolAddress((void**)&wh,  g_wh);
    cudaGetSymbolAddress((void**)&cnt, g_cnt);
    cudaGetSymbolAddress((void**)&cur, g_cur);
    cudaGetSymbolAddress((void**)&off, g_off);
    cudaGetSymbolAddress((void**)&eidx,g_eidx);
    cudaGetSymbolAddress((void**)&srcs,g_srcs);

    const float* F0 = (const float*)0;

    static bool attr_set = false;
    if (!attr_set){
        cudaFuncSetAttribute(k_gemm,   cudaFuncAttributeMaxDynamicSharedMemorySize, GEMM_SMEM);
        cudaFuncSetAttribute(k_gemm_h, cudaFuncAttributeMaxDynamicSharedMemorySize, HMMA_SMEM);
        attr_set = true;
    }

    const float dt  = 0.25f;
    const float dtc = dt / 6.0f;

    // prelude
    k_init      <<<B*SEQ*NN, HID>>>(inputs, w_in, b_in, hin, y, cnt, cur);
    k_wsplit    <<<(HID*HID/2+255)/256, 256>>>(w_gat, wh);
    k_csr_count <<<(E+255)/256, 256>>>(dst, cnt);
    k_csr_scan  <<<1, 1024>>>(cnt, off);

    // first RK4 stage-1 GEMM (does not need CSR)
    k_gemm_h<<<125,512,HMMA_SMEM>>>(y, F0, 0.f, wh, hp, el, er, a_l, a_r);

    k_csr_fill  <<<(E+255)/256, 256>>>(dst, off, cur, eidx);
    k_csr_sort  <<<NN, 32>>>(off, eidx, src, srcs);

    for (int idx = 0; idx < SEQ; idx++){
        for (int s = 0; s < 4; s++){
            if (!(idx == 0 && s == 0)){
                k_gemm_h<<<125,512,HMMA_SMEM>>>(y, F0, 0.f, wh, hp, el, er, a_l, a_r);
            }
            k_gat <<<NN,256>>>(hp, el, er, off, srcs, k1, F0,F0,F0,F0, 0.f);
            k_gemm_h<<<125,512,HMMA_SMEM>>>(y, k1, 0.5f*dt, wh, hp, el, er, a_l, a_r);
            k_gat <<<NN,256>>>(hp, el, er, off, srcs, k2, F0,F0,F0,F0, 0.f);
            k_gemm_h<<<125,512,HMMA_SMEM>>>(y, k2, 0.5f*dt, wh, hp, el, er, a_l, a_r);
            k_gat <<<NN,256>>>(hp, el, er, off, srcs, k3, F0,F0,F0,F0, 0.f);
            k_gemm_h<<<125,512,HMMA_SMEM>>>(y, k3, dt, wh, hp, el, er, a_l, a_r);
            k_gat <<<NN,256>>>(hp, el, er, off, srcs, y, y, k1, k2, k3, dtc);
        }
        if (idx > 0){
            // y = LN(tanh(y@w_W + h[idx]@w_U + b_W + b_U)) — LN fused (FFMA path)
            const float* hidx = hin + (size_t)idx * M_ROWS * HID;
            k_gemm<<<125,512,GEMM_SMEM>>>(y, w_W, hidx, w_U, b_W, b_U, y, 1, 1);
        } else {
            k_ln  <<<M_ROWS,128>>>(y, y);
        }
    }

    // out = tanh(y@w_o1 + b_o1) @ w_o2 + b_o2  (FFMA path)
    k_gemm<<<125,512,GEMM_SMEM>>>(y,   w_o1, F0, F0, b_o1, F0, tmp, 1, 0);
    k_gemm<<<125,512,GEMM_SMEM>>>(tmp, w_o2, F0, F0, b_o2, F0, out, 0, 0);
}